// round 4
// baseline (speedup 1.0000x reference)
#include <cuda_runtime.h>
#include <math.h>

// Problem constants
#define B_   2
#define S_   2048
#define D_   2048
#define H_   16
#define HD   128            // head dim
#define ROWS (B_*S_)        // 4096

// Scratch (alloc-free rule: __device__ globals)
__device__ float g_Q[(size_t)ROWS * D_];
__device__ float g_K[(size_t)ROWS * D_];
__device__ float g_V[(size_t)ROWS * D_];
__device__ float g_Y[(size_t)ROWS * D_];

// ----------------------------------------------------------------------------
// SGEMM: C[M,N] = A[M,K] @ B[N,K]^T   (both row-major, inner dim contiguous)
// 128x128 tile, BK=8, 256 threads, 8x8 per-thread microtile.
// ----------------------------------------------------------------------------
#define BM 128
#define BN 128
#define BK 8

__global__ __launch_bounds__(256) void sgemm_abt(const float* __restrict__ A,
                                                 const float* __restrict__ Bm,
                                                 float* __restrict__ C,
                                                 int M, int N, int K)
{
    __shared__ float As[BK][BM];
    __shared__ float Bs[BK][BN];

    const int tid = threadIdx.x;
    const int bx = blockIdx.x;          // N tile
    const int by = blockIdx.y;          // M tile
    const int tx = tid & 15;            // 0..15 (N dir)
    const int ty = tid >> 4;            // 0..15 (M dir)

    const float* Ab = A + (size_t)by * BM * K;
    const float* Bb = Bm + (size_t)bx * BN * K;

    const int lr = tid >> 1;            // 0..127 row within tile
    const int lc = (tid & 1) * 4;       // 0 or 4

    float acc[8][8];
#pragma unroll
    for (int i = 0; i < 8; i++)
#pragma unroll
        for (int j = 0; j < 8; j++) acc[i][j] = 0.f;

    for (int k0 = 0; k0 < K; k0 += BK) {
        float4 av = *(const float4*)(Ab + (size_t)lr * K + k0 + lc);
        float4 bv = *(const float4*)(Bb + (size_t)lr * K + k0 + lc);
        As[lc + 0][lr] = av.x; As[lc + 1][lr] = av.y;
        As[lc + 2][lr] = av.z; As[lc + 3][lr] = av.w;
        Bs[lc + 0][lr] = bv.x; Bs[lc + 1][lr] = bv.y;
        Bs[lc + 2][lr] = bv.z; Bs[lc + 3][lr] = bv.w;
        __syncthreads();

#pragma unroll
        for (int kk = 0; kk < BK; kk++) {
            float a[8], b[8];
            float4 a0 = *(const float4*)&As[kk][ty * 8];
            float4 a1 = *(const float4*)&As[kk][ty * 8 + 4];
            float4 b0 = *(const float4*)&Bs[kk][tx * 8];
            float4 b1 = *(const float4*)&Bs[kk][tx * 8 + 4];
            a[0]=a0.x; a[1]=a0.y; a[2]=a0.z; a[3]=a0.w;
            a[4]=a1.x; a[5]=a1.y; a[6]=a1.z; a[7]=a1.w;
            b[0]=b0.x; b[1]=b0.y; b[2]=b0.z; b[3]=b0.w;
            b[4]=b1.x; b[5]=b1.y; b[6]=b1.z; b[7]=b1.w;
#pragma unroll
            for (int i = 0; i < 8; i++)
#pragma unroll
                for (int j = 0; j < 8; j++)
                    acc[i][j] += a[i] * b[j];
        }
        __syncthreads();
    }

#pragma unroll
    for (int i = 0; i < 8; i++) {
        int r = by * BM + ty * 8 + i;
        float* Cr = C + (size_t)r * N + bx * BN + tx * 8;
        *(float4*)(Cr + 0) = make_float4(acc[i][0], acc[i][1], acc[i][2], acc[i][3]);
        *(float4*)(Cr + 4) = make_float4(acc[i][4], acc[i][5], acc[i][6], acc[i][7]);
    }
}

// ----------------------------------------------------------------------------
// Fused causal flash attention (fp32, online softmax).
// Grid: (S/AM query tiles, B*H). 256 threads.
// Q/K/V/Y all laid out [B*S, H*HD] (projection output layout); the head slice
// for (b,h) starts at element offset b*S*D + h*HD with row stride D.
// ----------------------------------------------------------------------------
#define AM 64
#define AN 64
#define SP (AN + 1)

// dyn smem layout (floats):
//   Qt  [HD][AM]   transposed, pre-scaled Q tile       8192
//   KV  [..]       K transposed [HD][AN]  OR  V [AN][HD] 8192
//   Ss  [AM][SP]   score / prob tile                    4160
//   mrow[AM] lrow[AM] corr[AM]                           192
#define ATTN_SMEM_FLOATS (HD*AM + AN*HD + AM*SP + 3*AM)
#define ATTN_SMEM_BYTES  (ATTN_SMEM_FLOATS * 4)

__global__ __launch_bounds__(256) void attn_kernel(const float* __restrict__ Qg,
                                                   const float* __restrict__ Kg,
                                                   const float* __restrict__ Vg,
                                                   float* __restrict__ Yg)
{
    extern __shared__ float sh[];
    float* Qt   = sh;                       // [HD][AM]
    float* KV   = Qt + HD * AM;             // K^T [HD][AN] or V [AN][HD]
    float* Ss   = KV + AN * HD;             // [AM][SP]
    float* mrow = Ss + AM * SP;
    float* lrow = mrow + AM;
    float* corr = lrow + AM;

    const int tid = threadIdx.x;
    const int qt  = blockIdx.x;
    const int bh  = blockIdx.y;
    const int b   = bh >> 4;
    const int h   = bh & 15;
    const size_t base = (size_t)b * S_ * D_ + (size_t)h * HD;
    const int q0 = qt * AM;
    const float scale = 0.08838834764831845f;   // 1/sqrt(128)

    // Load Q tile, transposed and pre-scaled
    for (int idx = tid; idx < AM * (HD / 4); idx += 256) {
        int r  = idx / (HD / 4);
        int c4 = (idx % (HD / 4)) * 4;
        float4 v = *(const float4*)(Qg + base + (size_t)(q0 + r) * D_ + c4);
        Qt[(c4 + 0) * AM + r] = v.x * scale;
        Qt[(c4 + 1) * AM + r] = v.y * scale;
        Qt[(c4 + 2) * AM + r] = v.z * scale;
        Qt[(c4 + 3) * AM + r] = v.w * scale;
    }
    if (tid < AM) { mrow[tid] = -3.0e38f; lrow[tid] = 0.f; }

    const int ty = tid >> 4;   // 0..15
    const int tx = tid & 15;   // 0..15
    // scores: rows ty*4..+4, cols tx*4..+4 ; output: rows ty*4..+4, cols tx*8..+8
    float acc[4][8];
#pragma unroll
    for (int i = 0; i < 4; i++)
#pragma unroll
        for (int j = 0; j < 8; j++) acc[i][j] = 0.f;

    for (int kt = 0; kt <= qt; kt++) {
        const int k0 = kt * AN;
        __syncthreads();   // prev PV done reading KV/Ss; init visible (kt=0)

        // Load K tile, transposed -> KV[dd][c]
        for (int idx = tid; idx < AN * (HD / 4); idx += 256) {
            int r  = idx / (HD / 4);
            int c4 = (idx % (HD / 4)) * 4;
            float4 v = *(const float4*)(Kg + base + (size_t)(k0 + r) * D_ + c4);
            KV[(c4 + 0) * AN + r] = v.x;
            KV[(c4 + 1) * AN + r] = v.y;
            KV[(c4 + 2) * AN + r] = v.z;
            KV[(c4 + 3) * AN + r] = v.w;
        }
        __syncthreads();

        // Scores: 4x4 per thread, S = Q K^T
        float s[4][4];
#pragma unroll
        for (int i = 0; i < 4; i++)
#pragma unroll
            for (int j = 0; j < 4; j++) s[i][j] = 0.f;

#pragma unroll 4
        for (int dd = 0; dd < HD; dd++) {
            float4 a4 = *(const float4*)&Qt[dd * AM + ty * 4];
            float4 b4 = *(const float4*)&KV[dd * AN + tx * 4];
            float a[4] = {a4.x, a4.y, a4.z, a4.w};
            float bb[4] = {b4.x, b4.y, b4.z, b4.w};
#pragma unroll
            for (int i = 0; i < 4; i++)
#pragma unroll
                for (int j = 0; j < 4; j++)
                    s[i][j] += a[i] * bb[j];
        }
        if (kt == qt) {   // causal mask on diagonal tile
#pragma unroll
            for (int i = 0; i < 4; i++)
#pragma unroll
                for (int j = 0; j < 4; j++)
                    if (k0 + tx * 4 + j > q0 + ty * 4 + i) s[i][j] = -3.0e38f;
        }
#pragma unroll
        for (int i = 0; i < 4; i++)
#pragma unroll
            for (int j = 0; j < 4; j++)
                Ss[(ty * 4 + i) * SP + tx * 4 + j] = s[i][j];
        __syncthreads();   // Ss ready; KV (K) free

        // Online softmax: one thread per query row
        if (tid < AM) {
            const int r = tid;
            float m_old = mrow[r];
            float mx = m_old;
#pragma unroll 8
            for (int j = 0; j < AN; j++) mx = fmaxf(mx, Ss[r * SP + j]);
            float cf = __expf(m_old - mx);
            float sum = 0.f;
#pragma unroll 8
            for (int j = 0; j < AN; j++) {
                float p = __expf(Ss[r * SP + j] - mx);
                Ss[r * SP + j] = p;
                sum += p;
            }
            mrow[r] = mx;
            lrow[r] = lrow[r] * cf + sum;
            corr[r] = cf;
        }
        // Load V tile (row-major [AN][HD]) into KV, overlapped with softmax
        for (int idx = tid; idx < AN * (HD / 4); idx += 256) {
            int r  = idx / (HD / 4);
            int c4 = (idx % (HD / 4)) * 4;
            *(float4*)&KV[r * HD + c4] =
                *(const float4*)(Vg + base + (size_t)(k0 + r) * D_ + c4);
        }
        __syncthreads();   // probs + corr + V ready

        // Rescale accumulators, then acc += P @ V
#pragma unroll
        for (int i = 0; i < 4; i++) {
            float cf = corr[ty * 4 + i];
#pragma unroll
            for (int j = 0; j < 8; j++) acc[i][j] *= cf;
        }
#pragma unroll 2
        for (int kk = 0; kk < AN; kk++) {
            float a[4];
#pragma unroll
            for (int i = 0; i < 4; i++) a[i] = Ss[(ty * 4 + i) * SP + kk];
            float4 b0 = *(const float4*)&KV[kk * HD + tx * 8];
            float4 b1 = *(const float4*)&KV[kk * HD + tx * 8 + 4];
            float bb[8] = {b0.x, b0.y, b0.z, b0.w, b1.x, b1.y, b1.z, b1.w};
#pragma unroll
            for (int i = 0; i < 4; i++)
#pragma unroll
                for (int j = 0; j < 8; j++)
                    acc[i][j] += a[i] * bb[j];
        }
    }

    __syncthreads();
    // Epilogue: divide by softmax denominator, write Y
#pragma unroll
    for (int i = 0; i < 4; i++) {
        int r = ty * 4 + i;
        float linv = 1.0f / lrow[r];
        float* Yr = Yg + base + (size_t)(q0 + r) * D_ + tx * 8;
        *(float4*)(Yr + 0) = make_float4(acc[i][0] * linv, acc[i][1] * linv,
                                         acc[i][2] * linv, acc[i][3] * linv);
        *(float4*)(Yr + 4) = make_float4(acc[i][4] * linv, acc[i][5] * linv,
                                         acc[i][6] * linv, acc[i][7] * linv);
    }
}

// ----------------------------------------------------------------------------
// kernel_launch
// inputs (metadata order): x, attn_mask, Wq, Wk, Wv, Wo
// attn_mask is pure causal (-1e9 above diagonal) -> handled analytically.
// ----------------------------------------------------------------------------
extern "C" void kernel_launch(void* const* d_in, const int* in_sizes, int n_in,
                              void* d_out, int out_size)
{
    const float* x  = (const float*)d_in[0];
    const float* Wq = (const float*)d_in[2];
    const float* Wk = (const float*)d_in[3];
    const float* Wv = (const float*)d_in[4];
    const float* Wo = (const float*)d_in[5];
    float* out = (float*)d_out;

    float *Q, *K, *V, *Y;
    cudaGetSymbolAddress((void**)&Q, g_Q);
    cudaGetSymbolAddress((void**)&K, g_K);
    cudaGetSymbolAddress((void**)&V, g_V);
    cudaGetSymbolAddress((void**)&Y, g_Y);

    dim3 gb(D_ / BN, ROWS / BM);   // (16, 32)
    dim3 tb(256);

    sgemm_abt<<<gb, tb>>>(x, Wq, Q, ROWS, D_, D_);
    sgemm_abt<<<gb, tb>>>(x, Wk, K, ROWS, D_, D_);
    sgemm_abt<<<gb, tb>>>(x, Wv, V, ROWS, D_, D_);

    cudaFuncSetAttribute(attn_kernel,
                         cudaFuncAttributeMaxDynamicSharedMemorySize,
                         ATTN_SMEM_BYTES);
    attn_kernel<<<dim3(S_ / AM, B_ * H_), tb, ATTN_SMEM_BYTES>>>(Q, K, V, Y);

    sgemm_abt<<<gb, tb>>>(Y, Wo, out, ROWS, D_, D_);
}

// round 6
// speedup vs baseline: 1.9452x; 1.9452x over previous
#include <cuda_runtime.h>
#include <math.h>
#include <stdint.h>

// Problem constants
#define B_   2
#define S_   2048
#define D_   2048
#define H_   16
#define HD   128            // head dim
#define ROWS (B_*S_)        // 4096

// Scratch (alloc-free rule: __device__ globals)
__device__ float g_Q[(size_t)ROWS * D_];
__device__ float g_K[(size_t)ROWS * D_];
__device__ float g_V[(size_t)ROWS * D_];
__device__ float g_Y[(size_t)ROWS * D_];

// ----------------------------------------------------------------------------
// Helpers
// ----------------------------------------------------------------------------
__device__ __forceinline__ uint32_t s2u(const void* p) {
    return (uint32_t)__cvta_generic_to_shared(p);
}
__device__ __forceinline__ uint32_t f2tf(float x) {
    uint32_t r;
    asm("cvt.rna.tf32.f32 %0, %1;" : "=r"(r) : "f"(x));
    return r;
}

#define MMA_TF32(d, a, b0v, b1v)                                               \
    asm volatile(                                                              \
        "mma.sync.aligned.m16n8k8.row.col.f32.tf32.tf32.f32 "                  \
        "{%0,%1,%2,%3},{%4,%5,%6,%7},{%8,%9},{%0,%1,%2,%3};"                   \
        : "+f"(d[0]), "+f"(d[1]), "+f"(d[2]), "+f"(d[3])                       \
        : "r"(a[0]), "r"(a[1]), "r"(a[2]), "r"(a[3]), "r"(b0v), "r"(b1v))

#define LDSM_X4(r0, r1, r2, r3, addr)                                          \
    asm volatile("ldmatrix.sync.aligned.m8n8.x4.shared.b16 {%0,%1,%2,%3},[%4];"\
                 : "=r"(r0), "=r"(r1), "=r"(r2), "=r"(r3) : "r"(addr))

// ----------------------------------------------------------------------------
// tf32 tensor-core GEMM: C[M,N] = A[M,K] @ B[N,K]^T (both row-major).
// Block 128x128, BK=16, 256 threads (8 warps as 2(M) x 4(N), warp tile 64x32).
// smem: padded rows (20 floats) -> ldmatrix conflict-free (stride 5 granules).
// fp32 -> tf32 conversion (round-to-nearest) once, on the LDG->STS path.
// ----------------------------------------------------------------------------
#define GBM 128
#define GBN 128
#define GBK 16
#define SROW 20                       // padded row length in floats
#define SSZB (GBM * SROW * 4)         // stage stride in bytes (10240)

__global__ __launch_bounds__(256, 2) void gemm_tf32_abt(
    const float* __restrict__ A, const float* __restrict__ Bm,
    float* __restrict__ C, int K, int N)
{
    __shared__ __align__(16) uint32_t As[2][GBM][SROW];
    __shared__ __align__(16) uint32_t Bs[2][GBN][SROW];

    const int tid  = threadIdx.x;
    const int lane = tid & 31;
    const int warp = tid >> 5;
    const int wm   = warp & 1;        // 0..1 -> 64 rows each
    const int wn   = warp >> 1;       // 0..3 -> 32 cols each
    const int bx = blockIdx.x, by = blockIdx.y;

    // Global load mapping: thread -> (row lr, float4-col lc/4); rows lr, lr+64
    const int lr = tid >> 2;          // 0..63
    const int lc = (tid & 3) * 4;     // 0,4,8,12
    const float* Ap = A + ((size_t)(by * GBM) + lr) * K + lc;
    const float* Bp = Bm + ((size_t)(bx * GBN) + lr) * K + lc;

    // ldmatrix per-lane address components
    const int a_row = ((lane >> 3) & 1) * 8 + (lane & 7);
    const int a_col = ((lane >> 4) & 1) * 4;
    const int b_row = ((lane >> 4) & 1) * 8 + (lane & 7);
    const int b_col = ((lane >> 3) & 1) * 4;

    const uint32_t aBase = s2u(&As[0][wm * 64 + a_row][a_col]);
    const uint32_t bBase = s2u(&Bs[0][wn * 32 + b_row][b_col]);

    float acc[4][4][4];
#pragma unroll
    for (int i = 0; i < 4; i++)
#pragma unroll
        for (int j = 0; j < 4; j++)
#pragma unroll
            for (int t = 0; t < 4; t++) acc[i][j][t] = 0.f;

    float4 ra0, ra1, rb0, rb1;

    // prologue: stage 0
    ra0 = *(const float4*)(Ap);
    ra1 = *(const float4*)(Ap + (size_t)64 * K);
    rb0 = *(const float4*)(Bp);
    rb1 = *(const float4*)(Bp + (size_t)64 * K);
    {
        uint4 u;
        u.x = f2tf(ra0.x); u.y = f2tf(ra0.y); u.z = f2tf(ra0.z); u.w = f2tf(ra0.w);
        *(uint4*)&As[0][lr][lc] = u;
        u.x = f2tf(ra1.x); u.y = f2tf(ra1.y); u.z = f2tf(ra1.z); u.w = f2tf(ra1.w);
        *(uint4*)&As[0][lr + 64][lc] = u;
        u.x = f2tf(rb0.x); u.y = f2tf(rb0.y); u.z = f2tf(rb0.z); u.w = f2tf(rb0.w);
        *(uint4*)&Bs[0][lr][lc] = u;
        u.x = f2tf(rb1.x); u.y = f2tf(rb1.y); u.z = f2tf(rb1.z); u.w = f2tf(rb1.w);
        *(uint4*)&Bs[0][lr + 64][lc] = u;
    }

    int cur = 0;
#pragma unroll 1
    for (int k0 = 0; k0 < K; k0 += GBK) {
        __syncthreads();
        const bool more = (k0 + GBK) < K;
        if (more) {
            ra0 = *(const float4*)(Ap + k0 + GBK);
            ra1 = *(const float4*)(Ap + (size_t)64 * K + k0 + GBK);
            rb0 = *(const float4*)(Bp + k0 + GBK);
            rb1 = *(const float4*)(Bp + (size_t)64 * K + k0 + GBK);
        }

        // compute current stage (2 k-steps of 8)
        const uint32_t aS = aBase + cur * SSZB;
        const uint32_t bS = bBase + cur * SSZB;
#pragma unroll
        for (int ks = 0; ks < 2; ks++) {
            uint32_t a[4][4], b[4][2];
#pragma unroll
            for (int mt = 0; mt < 4; mt++) {
                uint32_t addr = aS + mt * (16 * SROW * 4) + ks * 32;
                LDSM_X4(a[mt][0], a[mt][1], a[mt][2], a[mt][3], addr);
            }
#pragma unroll
            for (int p = 0; p < 2; p++) {
                uint32_t addr = bS + p * (16 * SROW * 4) + ks * 32;
                LDSM_X4(b[2 * p][0], b[2 * p][1], b[2 * p + 1][0], b[2 * p + 1][1], addr);
            }
#pragma unroll
            for (int mt = 0; mt < 4; mt++)
#pragma unroll
                for (int nt = 0; nt < 4; nt++)
                    MMA_TF32(acc[mt][nt], a[mt], b[nt][0], b[nt][1]);
        }

        if (more) {
            int nxt = cur ^ 1;
            uint4 u;
            u.x = f2tf(ra0.x); u.y = f2tf(ra0.y); u.z = f2tf(ra0.z); u.w = f2tf(ra0.w);
            *(uint4*)&As[nxt][lr][lc] = u;
            u.x = f2tf(ra1.x); u.y = f2tf(ra1.y); u.z = f2tf(ra1.z); u.w = f2tf(ra1.w);
            *(uint4*)&As[nxt][lr + 64][lc] = u;
            u.x = f2tf(rb0.x); u.y = f2tf(rb0.y); u.z = f2tf(rb0.z); u.w = f2tf(rb0.w);
            *(uint4*)&Bs[nxt][lr][lc] = u;
            u.x = f2tf(rb1.x); u.y = f2tf(rb1.y); u.z = f2tf(rb1.z); u.w = f2tf(rb1.w);
            *(uint4*)&Bs[nxt][lr + 64][lc] = u;
        }
        cur ^= 1;
    }

    // epilogue
#pragma unroll
    for (int mt = 0; mt < 4; mt++) {
        int r0 = by * GBM + wm * 64 + mt * 16 + (lane >> 2);
#pragma unroll
        for (int nt = 0; nt < 4; nt++) {
            int c0 = bx * GBN + wn * 32 + nt * 8 + (lane & 3) * 2;
            float* p0 = C + (size_t)r0 * N + c0;
            *(float2*)p0 = make_float2(acc[mt][nt][0], acc[mt][nt][1]);
            float* p1 = p0 + (size_t)8 * N;
            *(float2*)p1 = make_float2(acc[mt][nt][2], acc[mt][nt][3]);
        }
    }
}

// ----------------------------------------------------------------------------
// Fused causal flash attention (fp32, online softmax) — unchanged this round.
// ----------------------------------------------------------------------------
#define AM 64
#define AN 64
#define SP (AN + 1)

#define ATTN_SMEM_FLOATS (HD*AM + AN*HD + AM*SP + 3*AM)
#define ATTN_SMEM_BYTES  (ATTN_SMEM_FLOATS * 4)

__global__ __launch_bounds__(256) void attn_kernel(const float* __restrict__ Qg,
                                                   const float* __restrict__ Kg,
                                                   const float* __restrict__ Vg,
                                                   float* __restrict__ Yg)
{
    extern __shared__ float sh[];
    float* Qt   = sh;                       // [HD][AM]
    float* KV   = Qt + HD * AM;             // K^T [HD][AN] or V [AN][HD]
    float* Ss   = KV + AN * HD;             // [AM][SP]
    float* mrow = Ss + AM * SP;
    float* lrow = mrow + AM;
    float* corr = lrow + AM;

    const int tid = threadIdx.x;
    const int qt  = blockIdx.x;
    const int bh  = blockIdx.y;
    const int b   = bh >> 4;
    const int h   = bh & 15;
    const size_t base = (size_t)b * S_ * D_ + (size_t)h * HD;
    const int q0 = qt * AM;
    const float scale = 0.08838834764831845f;   // 1/sqrt(128)

    for (int idx = tid; idx < AM * (HD / 4); idx += 256) {
        int r  = idx / (HD / 4);
        int c4 = (idx % (HD / 4)) * 4;
        float4 v = *(const float4*)(Qg + base + (size_t)(q0 + r) * D_ + c4);
        Qt[(c4 + 0) * AM + r] = v.x * scale;
        Qt[(c4 + 1) * AM + r] = v.y * scale;
        Qt[(c4 + 2) * AM + r] = v.z * scale;
        Qt[(c4 + 3) * AM + r] = v.w * scale;
    }
    if (tid < AM) { mrow[tid] = -3.0e38f; lrow[tid] = 0.f; }

    const int ty = tid >> 4;
    const int tx = tid & 15;
    float acc[4][8];
#pragma unroll
    for (int i = 0; i < 4; i++)
#pragma unroll
        for (int j = 0; j < 8; j++) acc[i][j] = 0.f;

    for (int kt = 0; kt <= qt; kt++) {
        const int k0 = kt * AN;
        __syncthreads();

        for (int idx = tid; idx < AN * (HD / 4); idx += 256) {
            int r  = idx / (HD / 4);
            int c4 = (idx % (HD / 4)) * 4;
            float4 v = *(const float4*)(Kg + base + (size_t)(k0 + r) * D_ + c4);
            KV[(c4 + 0) * AN + r] = v.x;
            KV[(c4 + 1) * AN + r] = v.y;
            KV[(c4 + 2) * AN + r] = v.z;
            KV[(c4 + 3) * AN + r] = v.w;
        }
        __syncthreads();

        float s[4][4];
#pragma unroll
        for (int i = 0; i < 4; i++)
#pragma unroll
            for (int j = 0; j < 4; j++) s[i][j] = 0.f;

#pragma unroll 4
        for (int dd = 0; dd < HD; dd++) {
            float4 a4 = *(const float4*)&Qt[dd * AM + ty * 4];
            float4 b4 = *(const float4*)&KV[dd * AN + tx * 4];
            float a[4] = {a4.x, a4.y, a4.z, a4.w};
            float bb[4] = {b4.x, b4.y, b4.z, b4.w};
#pragma unroll
            for (int i = 0; i < 4; i++)
#pragma unroll
                for (int j = 0; j < 4; j++)
                    s[i][j] += a[i] * bb[j];
        }
        if (kt == qt) {
#pragma unroll
            for (int i = 0; i < 4; i++)
#pragma unroll
                for (int j = 0; j < 4; j++)
                    if (k0 + tx * 4 + j > q0 + ty * 4 + i) s[i][j] = -3.0e38f;
        }
#pragma unroll
        for (int i = 0; i < 4; i++)
#pragma unroll
            for (int j = 0; j < 4; j++)
                Ss[(ty * 4 + i) * SP + tx * 4 + j] = s[i][j];
        __syncthreads();

        if (tid < AM) {
            const int r = tid;
            float m_old = mrow[r];
            float mx = m_old;
#pragma unroll 8
            for (int j = 0; j < AN; j++) mx = fmaxf(mx, Ss[r * SP + j]);
            float cf = __expf(m_old - mx);
            float sum = 0.f;
#pragma unroll 8
            for (int j = 0; j < AN; j++) {
                float p = __expf(Ss[r * SP + j] - mx);
                Ss[r * SP + j] = p;
                sum += p;
            }
            mrow[r] = mx;
            lrow[r] = lrow[r] * cf + sum;
            corr[r] = cf;
        }
        for (int idx = tid; idx < AN * (HD / 4); idx += 256) {
            int r  = idx / (HD / 4);
            int c4 = (idx % (HD / 4)) * 4;
            *(float4*)&KV[r * HD + c4] =
                *(const float4*)(Vg + base + (size_t)(k0 + r) * D_ + c4);
        }
        __syncthreads();

#pragma unroll
        for (int i = 0; i < 4; i++) {
            float cf = corr[ty * 4 + i];
#pragma unroll
            for (int j = 0; j < 8; j++) acc[i][j] *= cf;
        }
#pragma unroll 2
        for (int kk = 0; kk < AN; kk++) {
            float a[4];
#pragma unroll
            for (int i = 0; i < 4; i++) a[i] = Ss[(ty * 4 + i) * SP + kk];
            float4 b0 = *(const float4*)&KV[kk * HD + tx * 8];
            float4 b1 = *(const float4*)&KV[kk * HD + tx * 8 + 4];
            float bb[8] = {b0.x, b0.y, b0.z, b0.w, b1.x, b1.y, b1.z, b1.w};
#pragma unroll
            for (int i = 0; i < 4; i++)
#pragma unroll
                for (int j = 0; j < 8; j++)
                    acc[i][j] += a[i] * bb[j];
        }
    }

    __syncthreads();
#pragma unroll
    for (int i = 0; i < 4; i++) {
        int r = ty * 4 + i;
        float linv = 1.0f / lrow[r];
        float* Yr = Yg + base + (size_t)(q0 + r) * D_ + tx * 8;
        *(float4*)(Yr + 0) = make_float4(acc[i][0] * linv, acc[i][1] * linv,
                                         acc[i][2] * linv, acc[i][3] * linv);
        *(float4*)(Yr + 4) = make_float4(acc[i][4] * linv, acc[i][5] * linv,
                                         acc[i][6] * linv, acc[i][7] * linv);
    }
}

// ----------------------------------------------------------------------------
// kernel_launch
// ----------------------------------------------------------------------------
extern "C" void kernel_launch(void* const* d_in, const int* in_sizes, int n_in,
                              void* d_out, int out_size)
{
    const float* x  = (const float*)d_in[0];
    const float* Wq = (const float*)d_in[2];
    const float* Wk = (const float*)d_in[3];
    const float* Wv = (const float*)d_in[4];
    const float* Wo = (const float*)d_in[5];
    float* out = (float*)d_out;

    float *Q, *K, *V, *Y;
    cudaGetSymbolAddress((void**)&Q, g_Q);
    cudaGetSymbolAddress((void**)&K, g_K);
    cudaGetSymbolAddress((void**)&V, g_V);
    cudaGetSymbolAddress((void**)&Y, g_Y);

    dim3 gb(D_ / GBN, ROWS / GBM);   // (16, 32)
    dim3 tb(256);

    gemm_tf32_abt<<<gb, tb>>>(x, Wq, Q, D_, D_);
    gemm_tf32_abt<<<gb, tb>>>(x, Wk, K, D_, D_);
    gemm_tf32_abt<<<gb, tb>>>(x, Wv, V, D_, D_);

    cudaFuncSetAttribute(attn_kernel,
                         cudaFuncAttributeMaxDynamicSharedMemorySize,
                         ATTN_SMEM_BYTES);
    attn_kernel<<<dim3(S_ / AM, B_ * H_), tb, ATTN_SMEM_BYTES>>>(Q, K, V, Y);

    gemm_tf32_abt<<<gb, tb>>>(Y, Wo, out, D_, D_);
}

// round 11
// speedup vs baseline: 3.1438x; 1.6161x over previous
#include <cuda_runtime.h>
#include <math.h>
#include <stdint.h>

// Problem constants
#define B_   2
#define S_   2048
#define D_   2048
#define H_   16
#define HD   128            // head dim
#define ROWS (B_*S_)        // 4096

// Scratch (alloc-free rule: __device__ globals)
__device__ float g_Q[(size_t)ROWS * D_];
__device__ float g_K[(size_t)ROWS * D_];
__device__ float g_V[(size_t)ROWS * D_];
__device__ float g_Y[(size_t)ROWS * D_];

// ----------------------------------------------------------------------------
// Helpers
// ----------------------------------------------------------------------------
__device__ __forceinline__ uint32_t s2u(const void* p) {
    return (uint32_t)__cvta_generic_to_shared(p);
}
__device__ __forceinline__ uint32_t f2tf(float x) {
    uint32_t r;
    asm("cvt.rna.tf32.f32 %0, %1;" : "=r"(r) : "f"(x));
    return r;
}

#define MMA_TF32(d, a, b0v, b1v)                                               \
    asm volatile(                                                              \
        "mma.sync.aligned.m16n8k8.row.col.f32.tf32.tf32.f32 "                  \
        "{%0,%1,%2,%3},{%4,%5,%6,%7},{%8,%9},{%0,%1,%2,%3};"                   \
        : "+f"(d[0]), "+f"(d[1]), "+f"(d[2]), "+f"(d[3])                       \
        : "r"(a[0]), "r"(a[1]), "r"(a[2]), "r"(a[3]), "r"(b0v), "r"(b1v))

#define LDSM_X4(r0, r1, r2, r3, addr)                                          \
    asm volatile("ldmatrix.sync.aligned.m8n8.x4.shared.b16 {%0,%1,%2,%3},[%4];"\
                 : "=r"(r0), "=r"(r1), "=r"(r2), "=r"(r3) : "r"(addr))

// ----------------------------------------------------------------------------
// tf32 tensor-core GEMM: C[M,N] = A[M,K] @ B[N,K]^T (both row-major).
// Block 128x128, BK=32, 256 threads (8 warps as 2(M) x 4(N), warp tile 64x32).
// Double-buffered dynamic smem, padded rows (36 floats -> 9 granules, odd ->
// ldmatrix conflict-free). fp32->tf32 rna conversion on the LDG->STS path.
// ----------------------------------------------------------------------------
#define GBM 128
#define GBN 128
#define GBK 32
#define SROW 36
#define STAGE_U32 (GBM * SROW)            // 4608 u32 = 18432 B
#define STAGE_B   (STAGE_U32 * 4)
#define GEMM_SMEM_BYTES (4 * STAGE_B)     // 73728

__global__ __launch_bounds__(256, 2) void gemm_tf32_abt(
    const float* __restrict__ A, const float* __restrict__ Bm,
    float* __restrict__ C, int K, int N)
{
    extern __shared__ uint32_t gs[];
    // layout: As stage0, As stage1, Bs stage0, Bs stage1

    const int tid  = threadIdx.x;
    const int lane = tid & 31;
    const int warp = tid >> 5;
    const int wm   = warp & 1;
    const int wn   = warp >> 1;
    const int bx = blockIdx.x, by = blockIdx.y;

    // Global load mapping: 2 threads per row, 4 float4 each
    const int lr = tid >> 1;            // 0..127
    const int lc = (tid & 1) * 4;       // 0 or 4
    const float* Ap = A + ((size_t)(by * GBM) + lr) * K + lc;
    const float* Bp = Bm + ((size_t)(bx * GBN) + lr) * K + lc;

    const int a_row = ((lane >> 3) & 1) * 8 + (lane & 7);
    const int a_col = ((lane >> 4) & 1) * 4;
    const int b_row = ((lane >> 4) & 1) * 8 + (lane & 7);
    const int b_col = ((lane >> 3) & 1) * 4;

    const uint32_t smem0 = s2u(gs);
    const uint32_t aBase = smem0 + ((wm * 64 + a_row) * SROW + a_col) * 4;
    const uint32_t bBase = smem0 + 2 * STAGE_B + ((wn * 32 + b_row) * SROW + b_col) * 4;

    float acc[4][4][4];
#pragma unroll
    for (int i = 0; i < 4; i++)
#pragma unroll
        for (int j = 0; j < 4; j++)
#pragma unroll
            for (int t = 0; t < 4; t++) acc[i][j][t] = 0.f;

    float4 ra[4], rb[4];

    // prologue: stage 0
#pragma unroll
    for (int j = 0; j < 4; j++) {
        ra[j] = *(const float4*)(Ap + j * 8);
        rb[j] = *(const float4*)(Bp + j * 8);
    }
#pragma unroll
    for (int j = 0; j < 4; j++) {
        uint4 u;
        u.x = f2tf(ra[j].x); u.y = f2tf(ra[j].y); u.z = f2tf(ra[j].z); u.w = f2tf(ra[j].w);
        *(uint4*)&gs[lr * SROW + lc + j * 8] = u;
        u.x = f2tf(rb[j].x); u.y = f2tf(rb[j].y); u.z = f2tf(rb[j].z); u.w = f2tf(rb[j].w);
        *(uint4*)&gs[2 * STAGE_U32 + lr * SROW + lc + j * 8] = u;
    }

    int cur = 0;
#pragma unroll 1
    for (int k0 = 0; k0 < K; k0 += GBK) {
        __syncthreads();
        const bool more = (k0 + GBK) < K;
        if (more) {
#pragma unroll
            for (int j = 0; j < 4; j++) {
                ra[j] = *(const float4*)(Ap + k0 + GBK + j * 8);
                rb[j] = *(const float4*)(Bp + k0 + GBK + j * 8);
            }
        }

        const uint32_t aS = aBase + cur * STAGE_B;
        const uint32_t bS = bBase + cur * STAGE_B;
#pragma unroll
        for (int ks = 0; ks < 4; ks++) {
            uint32_t a[4][4], b[4][2];
#pragma unroll
            for (int mt = 0; mt < 4; mt++)
                LDSM_X4(a[mt][0], a[mt][1], a[mt][2], a[mt][3],
                        aS + mt * (16 * SROW * 4) + ks * 32);
#pragma unroll
            for (int p = 0; p < 2; p++)
                LDSM_X4(b[2 * p][0], b[2 * p][1], b[2 * p + 1][0], b[2 * p + 1][1],
                        bS + p * (16 * SROW * 4) + ks * 32);
#pragma unroll
            for (int mt = 0; mt < 4; mt++)
#pragma unroll
                for (int nt = 0; nt < 4; nt++)
                    MMA_TF32(acc[mt][nt], a[mt], b[nt][0], b[nt][1]);
        }

        if (more) {
            const int nxt = cur ^ 1;
#pragma unroll
            for (int j = 0; j < 4; j++) {
                uint4 u;
                u.x = f2tf(ra[j].x); u.y = f2tf(ra[j].y); u.z = f2tf(ra[j].z); u.w = f2tf(ra[j].w);
                *(uint4*)&gs[nxt * STAGE_U32 + lr * SROW + lc + j * 8] = u;
                u.x = f2tf(rb[j].x); u.y = f2tf(rb[j].y); u.z = f2tf(rb[j].z); u.w = f2tf(rb[j].w);
                *(uint4*)&gs[(2 + nxt) * STAGE_U32 + lr * SROW + lc + j * 8] = u;
            }
        }
        cur ^= 1;
    }

    // epilogue
#pragma unroll
    for (int mt = 0; mt < 4; mt++) {
        int r0 = by * GBM + wm * 64 + mt * 16 + (lane >> 2);
#pragma unroll
        for (int nt = 0; nt < 4; nt++) {
            int c0 = bx * GBN + wn * 32 + nt * 8 + (lane & 3) * 2;
            float* p0 = C + (size_t)r0 * N + c0;
            *(float2*)p0 = make_float2(acc[mt][nt][0], acc[mt][nt][1]);
            float* p1 = p0 + (size_t)8 * N;
            *(float2*)p1 = make_float2(acc[mt][nt][2], acc[mt][nt][3]);
        }
    }
}

// ----------------------------------------------------------------------------
// Tensor-core causal flash attention (tf32 mma, fp32 softmax/accum).
// Block: 128 q-rows of one (b,h); 256 threads = 8 warps, 16 q-rows per warp.
// Key tiles of 64. K row-major in smem (mma B operand), V transposed [HD][64].
// Q fragments live in registers for the whole block.
// ----------------------------------------------------------------------------
#define AQ 128
#define AK 64
#define KSR 132                      // Ks row stride (floats), 33 granules
#define VSR 68                       // Vt/Ps row stride, 17 granules
#define KS_OFF 0                     // [64][132]  = 8448 u32
#define VT_OFF (64 * KSR)            // [128][68] = 8704 u32
#define PS_OFF (VT_OFF + 128 * VSR)  // [128][68] = 8704 u32
#define ATTN_SMEM_BYTES ((PS_OFF + 128 * VSR) * 4)   // 103424

__global__ __launch_bounds__(256, 1) void attn_tc(const float* __restrict__ Qg,
                                                  const float* __restrict__ Kg,
                                                  const float* __restrict__ Vg,
                                                  float* __restrict__ Yg)
{
    extern __shared__ uint32_t ash[];
    uint32_t* Ks  = ash + KS_OFF;
    uint32_t* Vt  = ash + VT_OFF;
    uint32_t* Ps  = ash + PS_OFF;
    uint32_t* Qst = ash;             // overlay [128][132] staging (<= total)

    const int tid  = threadIdx.x;
    const int lane = tid & 31;
    const int warp = tid >> 5;
    const int bx = gridDim.x - 1 - blockIdx.x;   // big causal blocks first
    const int bh = blockIdx.y;
    const int b  = bh >> 4;
    const int h  = bh & 15;
    const size_t base = (size_t)b * S_ * D_ + (size_t)h * HD;
    const int q0 = bx * AQ;
    const int qw = q0 + warp * 16;               // warp's first q row
    const float scale = 0.08838834764831845f;    // 1/sqrt(128)

    const int a_row = ((lane >> 3) & 1) * 8 + (lane & 7);
    const int a_col = ((lane >> 4) & 1) * 4;
    const int b_row = ((lane >> 4) & 1) * 8 + (lane & 7);
    const int b_col = ((lane >> 3) & 1) * 4;

    // ---- stage Q (scaled, tf32) and hoist fragments to registers ----
    {
        const int r = tid >> 1;
#pragma unroll
        for (int j = 0; j < 16; j++) {
            const int c4 = (tid & 1) * 4 + j * 8;
            float4 v = *(const float4*)(Qg + base + (size_t)(q0 + r) * D_ + c4);
            uint4 u;
            u.x = f2tf(v.x * scale); u.y = f2tf(v.y * scale);
            u.z = f2tf(v.z * scale); u.w = f2tf(v.w * scale);
            *(uint4*)&Qst[r * KSR + c4] = u;
        }
    }
    __syncthreads();

    uint32_t qf[16][4];
    {
        const uint32_t qb = s2u(Qst) + ((warp * 16 + a_row) * KSR + a_col) * 4;
#pragma unroll
        for (int ks = 0; ks < 16; ks++)
            LDSM_X4(qf[ks][0], qf[ks][1], qf[ks][2], qf[ks][3], qb + ks * 32);
    }
    __syncthreads();   // staging region about to be reused for K

    float m0 = -3.0e38f, m1 = -3.0e38f, l0 = 0.f, l1 = 0.f;
    float of[16][4];
#pragma unroll
    for (int i = 0; i < 16; i++)
#pragma unroll
        for (int t = 0; t < 4; t++) of[i][t] = 0.f;

    const uint32_t kb = s2u(Ks) + (b_row * KSR + b_col) * 4;
    const uint32_t vb = s2u(Vt) + (b_row * VSR + b_col) * 4;
    const uint32_t pb = s2u(Ps) + ((warp * 16 + a_row) * VSR + a_col) * 4;

    const int ntiles = 2 * bx + 2;
#pragma unroll 1
    for (int kt = 0; kt < ntiles; kt++) {
        const int k0 = kt * AK;
        __syncthreads();   // previous tile's smem reads complete

        // load K tile [64][128] row-major
        {
            const int r = tid >> 2;
#pragma unroll
            for (int j = 0; j < 8; j++) {
                const int c4 = (tid & 3) * 4 + j * 16;
                float4 v = *(const float4*)(Kg + base + (size_t)(k0 + r) * D_ + c4);
                uint4 u;
                u.x = f2tf(v.x); u.y = f2tf(v.y); u.z = f2tf(v.z); u.w = f2tf(v.w);
                *(uint4*)&Ks[r * KSR + c4] = u;
            }
        }
        // load V tile transposed -> Vt[hd][key]
        {
            const int r  = tid & 63;
            const int cb = (tid >> 6) * 4;
#pragma unroll
            for (int j = 0; j < 8; j++) {
                const int c4 = cb + j * 16;
                float4 v = *(const float4*)(Vg + base + (size_t)(k0 + r) * D_ + c4);
                Vt[(c4 + 0) * VSR + r] = f2tf(v.x);
                Vt[(c4 + 1) * VSR + r] = f2tf(v.y);
                Vt[(c4 + 2) * VSR + r] = f2tf(v.z);
                Vt[(c4 + 3) * VSR + r] = f2tf(v.w);
            }
        }
        __syncthreads();

        if (k0 <= qw + 15) {   // warp has at least one unmasked row
            // ---- S = Q K^T ----
            float s[8][4];
#pragma unroll
            for (int nt = 0; nt < 8; nt++)
#pragma unroll
                for (int t = 0; t < 4; t++) s[nt][t] = 0.f;

#pragma unroll
            for (int ks = 0; ks < 16; ks++) {
                uint32_t bb[8][2];
#pragma unroll
                for (int p = 0; p < 4; p++)
                    LDSM_X4(bb[2 * p][0], bb[2 * p][1], bb[2 * p + 1][0], bb[2 * p + 1][1],
                            kb + p * (16 * KSR * 4) + ks * 32);
#pragma unroll
                for (int nt = 0; nt < 8; nt++)
                    MMA_TF32(s[nt], qf[ks], bb[nt][0], bb[nt][1]);
            }

            // causal mask (diagonal tiles only)
            if (k0 + 63 > qw) {
                const int r0g = qw + (lane >> 2);
                const int c0g = k0 + (lane & 3) * 2;
#pragma unroll
                for (int nt = 0; nt < 8; nt++) {
                    const int c = c0g + nt * 8;
                    if (c     > r0g)     s[nt][0] = -3.0e38f;
                    if (c + 1 > r0g)     s[nt][1] = -3.0e38f;
                    if (c     > r0g + 8) s[nt][2] = -3.0e38f;
                    if (c + 1 > r0g + 8) s[nt][3] = -3.0e38f;
                }
            }

            // ---- online softmax (rows r0 = lane>>2 and r0+8) ----
            float mx0 = -3.0e38f, mx1 = -3.0e38f;
#pragma unroll
            for (int nt = 0; nt < 8; nt++) {
                mx0 = fmaxf(mx0, fmaxf(s[nt][0], s[nt][1]));
                mx1 = fmaxf(mx1, fmaxf(s[nt][2], s[nt][3]));
            }
            mx0 = fmaxf(mx0, __shfl_xor_sync(0xffffffffu, mx0, 1));
            mx0 = fmaxf(mx0, __shfl_xor_sync(0xffffffffu, mx0, 2));
            mx1 = fmaxf(mx1, __shfl_xor_sync(0xffffffffu, mx1, 1));
            mx1 = fmaxf(mx1, __shfl_xor_sync(0xffffffffu, mx1, 2));

            const float mn0 = fmaxf(m0, mx0);
            const float mn1 = fmaxf(m1, mx1);
            const float cf0 = __expf(m0 - mn0);
            const float cf1 = __expf(m1 - mn1);

            float sum0 = 0.f, sum1 = 0.f;
            const int prow = warp * 16 + (lane >> 2);
            const int pcol = (lane & 3) * 2;
#pragma unroll
            for (int nt = 0; nt < 8; nt++) {
                float p0 = __expf(s[nt][0] - mn0);
                float p1 = __expf(s[nt][1] - mn0);
                float p2 = __expf(s[nt][2] - mn1);
                float p3 = __expf(s[nt][3] - mn1);
                sum0 += p0 + p1;
                sum1 += p2 + p3;
                uint32_t* d0 = &Ps[prow * VSR + pcol + nt * 8];
                d0[0] = f2tf(p0); d0[1] = f2tf(p1);
                uint32_t* d1 = &Ps[(prow + 8) * VSR + pcol + nt * 8];
                d1[0] = f2tf(p2); d1[1] = f2tf(p3);
            }
            sum0 += __shfl_xor_sync(0xffffffffu, sum0, 1);
            sum0 += __shfl_xor_sync(0xffffffffu, sum0, 2);
            sum1 += __shfl_xor_sync(0xffffffffu, sum1, 1);
            sum1 += __shfl_xor_sync(0xffffffffu, sum1, 2);

            m0 = mn0; m1 = mn1;
            l0 = l0 * cf0 + sum0;
            l1 = l1 * cf1 + sum1;

#pragma unroll
            for (int nt = 0; nt < 16; nt++) {
                of[nt][0] *= cf0; of[nt][1] *= cf0;
                of[nt][2] *= cf1; of[nt][3] *= cf1;
            }

            __syncwarp();   // Ps writes visible to ldmatrix across lanes

            // ---- O += P V ----
#pragma unroll
            for (int ks = 0; ks < 8; ks++) {
                uint32_t pa[4];
                LDSM_X4(pa[0], pa[1], pa[2], pa[3], pb + ks * 32);
#pragma unroll
                for (int np = 0; np < 8; np++) {
                    uint32_t v0, v1, v2, v3;
                    LDSM_X4(v0, v1, v2, v3, vb + np * (16 * VSR * 4) + ks * 32);
                    MMA_TF32(of[2 * np],     pa, v0, v1);
                    MMA_TF32(of[2 * np + 1], pa, v2, v3);
                }
            }
        }
    }

    // ---- epilogue ----
    const float li0 = 1.0f / l0;
    const float li1 = 1.0f / l1;
    const int r0 = q0 + warp * 16 + (lane >> 2);
#pragma unroll
    for (int nt = 0; nt < 16; nt++) {
        const int c = nt * 8 + (lane & 3) * 2;
        float* p = Yg + base + (size_t)r0 * D_ + c;
        *(float2*)p = make_float2(of[nt][0] * li0, of[nt][1] * li0);
        *(float2*)(p + (size_t)8 * D_) = make_float2(of[nt][2] * li1, of[nt][3] * li1);
    }
}

// ----------------------------------------------------------------------------
// kernel_launch
// ----------------------------------------------------------------------------
extern "C" void kernel_launch(void* const* d_in, const int* in_sizes, int n_in,
                              void* d_out, int out_size)
{
    const float* x  = (const float*)d_in[0];
    const float* Wq = (const float*)d_in[2];
    const float* Wk = (const float*)d_in[3];
    const float* Wv = (const float*)d_in[4];
    const float* Wo = (const float*)d_in[5];
    float* out = (float*)d_out;

    float *Q, *K, *V, *Y;
    cudaGetSymbolAddress((void**)&Q, g_Q);
    cudaGetSymbolAddress((void**)&K, g_K);
    cudaGetSymbolAddress((void**)&V, g_V);
    cudaGetSymbolAddress((void**)&Y, g_Y);

    static int configured = 0;
    if (!configured) {
        cudaFuncSetAttribute(gemm_tf32_abt,
                             cudaFuncAttributeMaxDynamicSharedMemorySize,
                             GEMM_SMEM_BYTES);
        cudaFuncSetAttribute(attn_tc,
                             cudaFuncAttributeMaxDynamicSharedMemorySize,
                             ATTN_SMEM_BYTES);
        configured = 1;
    }

    dim3 gb(D_ / GBN, ROWS / GBM);   // (16, 32)
    dim3 tb(256);

    gemm_tf32_abt<<<gb, tb, GEMM_SMEM_BYTES>>>(x, Wq, Q, D_, D_);
    gemm_tf32_abt<<<gb, tb, GEMM_SMEM_BYTES>>>(x, Wk, K, D_, D_);
    gemm_tf32_abt<<<gb, tb, GEMM_SMEM_BYTES>>>(x, Wv, V, D_, D_);

    attn_tc<<<dim3(S_ / AQ, B_ * H_), tb, ATTN_SMEM_BYTES>>>(Q, K, V, Y);

    gemm_tf32_abt<<<gb, tb, GEMM_SMEM_BYTES>>>(Y, Wo, out, D_, D_);
}

// round 17
// speedup vs baseline: 4.3440x; 1.3818x over previous
#include <cuda_runtime.h>
#include <math.h>
#include <stdint.h>

// Problem constants
#define B_   2
#define S_   2048
#define D_   2048
#define H_   16
#define HD   128
#define ROWS (B_*S_)        // 4096

// Scratch (alloc-free rule: __device__ globals)
__device__ float g_Q[(size_t)ROWS * D_];
__device__ float g_K[(size_t)ROWS * D_];
__device__ float g_V[(size_t)ROWS * D_];
__device__ float g_Vt[(size_t)ROWS * D_];          // V transposed per batch: [b][d][s]
__device__ float g_Y[(size_t)ROWS * D_];
__device__ float g_Xt[(size_t)ROWS * D_];          // rna-rounded x
__device__ float g_Wt[4][(size_t)D_ * D_];         // rna-rounded Wq,Wk,Wv,Wo

// ----------------------------------------------------------------------------
// Helpers
// ----------------------------------------------------------------------------
__device__ __forceinline__ uint32_t s2u(const void* p) {
    return (uint32_t)__cvta_generic_to_shared(p);
}
__device__ __forceinline__ uint32_t f2tf(float x) {
    uint32_t r;
    asm("cvt.rna.tf32.f32 %0, %1;" : "=r"(r) : "f"(x));
    return r;
}
__device__ __forceinline__ void cp16(uint32_t dst, const void* src) {
    asm volatile("cp.async.cg.shared.global [%0], [%1], 16;"
                 :: "r"(dst), "l"(src) : "memory");
}
__device__ __forceinline__ void cp_commit() {
    asm volatile("cp.async.commit_group;" ::: "memory");
}

#define MMA_TF32(d, a, b0v, b1v)                                               \
    asm volatile(                                                              \
        "mma.sync.aligned.m16n8k8.row.col.f32.tf32.tf32.f32 "                  \
        "{%0,%1,%2,%3},{%4,%5,%6,%7},{%8,%9},{%0,%1,%2,%3};"                   \
        : "+f"(d[0]), "+f"(d[1]), "+f"(d[2]), "+f"(d[3])                       \
        : "r"(a[0]), "r"(a[1]), "r"(a[2]), "r"(a[3]), "r"(b0v), "r"(b1v))

#define LDSM_X4(r0, r1, r2, r3, addr)                                          \
    asm volatile("ldmatrix.sync.aligned.m8n8.x4.shared.b16 {%0,%1,%2,%3},[%4];"\
                 : "=r"(r0), "=r"(r1), "=r"(r2), "=r"(r3) : "r"(addr))

// ----------------------------------------------------------------------------
// cvt kernel: fp32 -> tf32(rna) bit patterns
// ----------------------------------------------------------------------------
__global__ __launch_bounds__(256) void cvt_rna_k(const float4* __restrict__ in,
                                                 float4* __restrict__ out, int n4)
{
    int i = blockIdx.x * 256 + threadIdx.x;
    if (i < n4) {
        float4 v = in[i];
        float4 o;
        o.x = __uint_as_float(f2tf(v.x));
        o.y = __uint_as_float(f2tf(v.y));
        o.z = __uint_as_float(f2tf(v.z));
        o.w = __uint_as_float(f2tf(v.w));
        out[i] = o;
    }
}

// ----------------------------------------------------------------------------
// Tiled transpose: out[b][d][s] = in[b][s][d]   (2048x2048 per batch)
// ----------------------------------------------------------------------------
__global__ __launch_bounds__(256) void transpose_k(const float* __restrict__ in,
                                                   float* __restrict__ out)
{
    __shared__ float t[32][33];
    const int b  = blockIdx.z;
    const int s0 = blockIdx.x * 32;
    const int d0 = blockIdx.y * 32;
    const float* ib = in  + (size_t)b * S_ * D_;
    float*       ob = out + (size_t)b * S_ * D_;
    const int tx = threadIdx.x & 31;
    const int ty = threadIdx.x >> 5;       // 0..7
#pragma unroll
    for (int i = 0; i < 4; i++)
        t[ty + i * 8][tx] = ib[(size_t)(s0 + ty + i * 8) * D_ + d0 + tx];
    __syncthreads();
#pragma unroll
    for (int i = 0; i < 4; i++)
        ob[(size_t)(d0 + ty + i * 8) * S_ + s0 + tx] = t[tx][ty + i * 8];
}

// ----------------------------------------------------------------------------
// tf32 mma.sync GEMM v3: C[M,N] = A[M,K] @ B[N,K]^T, K=2048.
// Block 128x128, BK=16, 3-stage cp.async pipeline, 256 threads
// (8 warps 2(M)x4(N), warp tile 64x32). Padded rows (20 floats) keep
// ldmatrix conflict-free. Inputs must be tf32-pre-rounded bit patterns.
// round_out=1 -> outputs written tf32(rna)-rounded (feeds downstream mma).
// ----------------------------------------------------------------------------
#define GBM 128
#define GBN 128
#define GBK 16
#define SROW 20
#define STG_U32 (256 * SROW)            // A rows [0,128) + B rows [128,256)
#define STG_B   (STG_U32 * 4)           // 20480
#define NSTAGE 3
#define GEMM_SMEM_BYTES (NSTAGE * STG_B)   // 61440

__global__ __launch_bounds__(256, 2) void gemm_tf32(
    const float* __restrict__ A, const float* __restrict__ Bm,
    float* __restrict__ C, int round_out)
{
    extern __shared__ uint32_t gs[];
    const uint32_t sb = s2u(gs);
    const int tid  = threadIdx.x;
    const int lane = tid & 31;
    const int warp = tid >> 5;
    const int wm   = warp & 1;
    const int wn   = warp >> 1;
    const int n0 = blockIdx.x * GBN;
    const int m0 = blockIdx.y * GBM;
    const float* Ag = A  + (size_t)m0 * D_;
    const float* Bg = Bm + (size_t)n0 * D_;

    const int a_row = ((lane >> 3) & 1) * 8 + (lane & 7);
    const int a_col = ((lane >> 4) & 1) * 4;
    const int b_row = ((lane >> 4) & 1) * 8 + (lane & 7);
    const int b_col = ((lane >> 3) & 1) * 4;
    const uint32_t aBase = sb + ((wm * 64 + a_row) * SROW + a_col) * 4;
    const uint32_t bBase = sb + (128 * SROW + (wn * 32 + b_row) * SROW + b_col) * 4;

    // cp.async fill mapping: 1024 granules (256 rows x 4x16B), 4 per thread
    const int f_row = tid >> 2;             // reused with +64 offsets? no: row = G>>2
    (void)f_row;

    float acc[4][4][4];
#pragma unroll
    for (int i = 0; i < 4; i++)
#pragma unroll
        for (int j = 0; j < 4; j++)
#pragma unroll
            for (int t = 0; t < 4; t++) acc[i][j][t] = 0.f;

    // prologue: stages 0,1
#pragma unroll
    for (int st = 0; st < 2; st++) {
        const uint32_t base = sb + st * STG_B;
        const int k0 = st * GBK;
#pragma unroll
        for (int j = 0; j < 4; j++) {
            int G = tid + j * 256;
            int row = G >> 2, gc = G & 3;
            const float* src = (row < 128)
                ? Ag + (size_t)row * D_ + k0 + gc * 4
                : Bg + (size_t)(row - 128) * D_ + k0 + gc * 4;
            cp16(base + (row * SROW + gc * 4) * 4, src);
        }
        cp_commit();
    }

    const int NIT = D_ / GBK;               // 128
#pragma unroll 1
    for (int it = 0; it < NIT; it++) {
        const int s = it % NSTAGE;
        if (it + 2 < NIT) {
            asm volatile("cp.async.wait_group 1;" ::: "memory");
        } else {
            asm volatile("cp.async.wait_group 0;" ::: "memory");
        }
        __syncthreads();

        if (it + 2 < NIT) {                 // refill stage (it+2)%3
            const uint32_t base = sb + ((it + 2) % NSTAGE) * STG_B;
            const int k0 = (it + 2) * GBK;
#pragma unroll
            for (int j = 0; j < 4; j++) {
                int G = tid + j * 256;
                int row = G >> 2, gc = G & 3;
                const float* src = (row < 128)
                    ? Ag + (size_t)row * D_ + k0 + gc * 4
                    : Bg + (size_t)(row - 128) * D_ + k0 + gc * 4;
                cp16(base + (row * SROW + gc * 4) * 4, src);
            }
            cp_commit();
        }

        const uint32_t aS = aBase + s * STG_B;
        const uint32_t bS = bBase + s * STG_B;
#pragma unroll
        for (int ks = 0; ks < 2; ks++) {
            uint32_t a[4][4], b[4][2];
#pragma unroll
            for (int mt = 0; mt < 4; mt++)
                LDSM_X4(a[mt][0], a[mt][1], a[mt][2], a[mt][3],
                        aS + mt * (16 * SROW * 4) + ks * 32);
#pragma unroll
            for (int p = 0; p < 2; p++)
                LDSM_X4(b[2 * p][0], b[2 * p][1], b[2 * p + 1][0], b[2 * p + 1][1],
                        bS + p * (16 * SROW * 4) + ks * 32);
#pragma unroll
            for (int mt = 0; mt < 4; mt++)
#pragma unroll
                for (int nt = 0; nt < 4; nt++)
                    MMA_TF32(acc[mt][nt], a[mt], b[nt][0], b[nt][1]);
        }
    }

    // epilogue
#pragma unroll
    for (int mt = 0; mt < 4; mt++) {
        int r0 = m0 + wm * 64 + mt * 16 + (lane >> 2);
#pragma unroll
        for (int nt = 0; nt < 4; nt++) {
            int c0 = n0 + wn * 32 + nt * 8 + (lane & 3) * 2;
            float v0 = acc[mt][nt][0], v1 = acc[mt][nt][1];
            float v2 = acc[mt][nt][2], v3 = acc[mt][nt][3];
            if (round_out) {
                v0 = __uint_as_float(f2tf(v0)); v1 = __uint_as_float(f2tf(v1));
                v2 = __uint_as_float(f2tf(v2)); v3 = __uint_as_float(f2tf(v3));
            }
            float* p0 = C + (size_t)r0 * D_ + c0;
            *(float2*)p0 = make_float2(v0, v1);
            *(float2*)(p0 + (size_t)8 * D_) = make_float2(v2, v3);
        }
    }
}

// ----------------------------------------------------------------------------
// Tensor-core causal flash attention v2 (mma.sync tf32, fp32 softmax/accum).
// cp.async double-buffered K and V-transposed tiles; loads overlap compute.
// Block: 128 q-rows of one (b,h); 256 threads = 8 warps, 16 q-rows per warp.
// Q/K/V are tf32-pre-rounded in global. Vt global layout: [b][d][s].
// ----------------------------------------------------------------------------
#define AQ 128
#define AK 64
#define KSR 132                       // K row stride (floats), 33 granules
#define VSR 68                        // Vt/Ps row stride, 17 granules
#define KS0 0                         // [64][132]
#define KS1 (64 * KSR)                // 8448
#define VT0 (2 * 64 * KSR)            // 16896  [128][68]
#define VT1 (VT0 + 128 * VSR)         // 25600
#define PSO (VT0 + 2 * 128 * VSR)     // 34304  [128][68]
#define ATTN_SMEM_BYTES ((PSO + 128 * VSR) * 4)   // 172032

__global__ __launch_bounds__(256, 1) void attn_tc(const float* __restrict__ Qg,
                                                  const float* __restrict__ Kg,
                                                  const float* __restrict__ Vtg,
                                                  float* __restrict__ Yg)
{
    extern __shared__ uint32_t ash[];
    uint32_t* Ps  = ash + PSO;
    uint32_t* Qst = ash;              // overlay [128][132] staging (= Ks0+Ks1)

    const int tid  = threadIdx.x;
    const int lane = tid & 31;
    const int warp = tid >> 5;
    const int bx = gridDim.x - 1 - blockIdx.x;   // big causal blocks first
    const int bh = blockIdx.y;
    const int b  = bh >> 4;
    const int h  = bh & 15;
    const size_t base  = (size_t)b * S_ * D_ + (size_t)h * HD;
    const size_t vbase = (size_t)bh * HD * S_;   // [b][h*128..][s]
    const int q0 = bx * AQ;
    const int qw = q0 + warp * 16;
    const float scale = 0.08838834764831845f;    // 1/sqrt(128)

    const int a_row = ((lane >> 3) & 1) * 8 + (lane & 7);
    const int a_col = ((lane >> 4) & 1) * 4;
    const int b_row = ((lane >> 4) & 1) * 8 + (lane & 7);
    const int b_col = ((lane >> 3) & 1) * 4;

    // ---- stage Q (scaled, tf32) and hoist fragments to registers ----
    {
        const int r = tid >> 1;
#pragma unroll
        for (int j = 0; j < 16; j++) {
            const int c4 = (tid & 1) * 4 + j * 8;
            float4 v = *(const float4*)(Qg + base + (size_t)(q0 + r) * D_ + c4);
            uint4 u;
            u.x = f2tf(v.x * scale); u.y = f2tf(v.y * scale);
            u.z = f2tf(v.z * scale); u.w = f2tf(v.w * scale);
            *(uint4*)&Qst[r * KSR + c4] = u;
        }
    }
    __syncthreads();

    uint32_t qf[16][4];
    {
        const uint32_t qb = s2u(Qst) + ((warp * 16 + a_row) * KSR + a_col) * 4;
#pragma unroll
        for (int ks = 0; ks < 16; ks++)
            LDSM_X4(qf[ks][0], qf[ks][1], qf[ks][2], qf[ks][3], qb + ks * 32);
    }
    __syncthreads();   // staging region about to be reused for K

    float m0 = -3.0e38f, m1 = -3.0e38f, l0 = 0.f, l1 = 0.f;
    float of[16][4];
#pragma unroll
    for (int i = 0; i < 16; i++)
#pragma unroll
        for (int t = 0; t < 4; t++) of[i][t] = 0.f;

    const uint32_t sb = s2u(ash);
    const uint32_t ksB[2] = { sb + KS0 * 4, sb + KS1 * 4 };
    const uint32_t vtB[2] = { sb + VT0 * 4, sb + VT1 * 4 };
    const uint32_t pb = s2u(Ps) + ((warp * 16 + a_row) * VSR + a_col) * 4;

    // preload tile 0 into buffer 0
    {
#pragma unroll
        for (int j = 0; j < 8; j++) {       // K: 64 rows x 32 granules
            int G = tid + j * 256;
            int row = G >> 5, gc = G & 31;
            cp16(ksB[0] + (row * KSR) * 4 + gc * 16,
                 Kg + base + (size_t)row * D_ + gc * 4);
        }
#pragma unroll
        for (int j = 0; j < 8; j++) {       // Vt: 128 rows x 16 granules
            int G = tid + j * 256;
            int row = G >> 4, gc = G & 15;
            cp16(vtB[0] + (row * VSR) * 4 + gc * 16,
                 Vtg + vbase + (size_t)row * S_ + gc * 4);
        }
        cp_commit();
        asm volatile("cp.async.wait_group 0;" ::: "memory");
    }
    __syncthreads();

    int buf = 0;
    const int ntiles = 2 * bx + 2;
#pragma unroll 1
    for (int kt = 0; kt < ntiles; kt++) {
        const int k0 = kt * AK;
        const bool more = (kt + 1) < ntiles;

        // issue next tile's loads into the other buffer
        if (more) {
            const int kn = k0 + AK;
#pragma unroll
            for (int j = 0; j < 8; j++) {
                int G = tid + j * 256;
                int row = G >> 5, gc = G & 31;
                cp16(ksB[buf ^ 1] + (row * KSR) * 4 + gc * 16,
                     Kg + base + (size_t)(kn + row) * D_ + gc * 4);
            }
#pragma unroll
            for (int j = 0; j < 8; j++) {
                int G = tid + j * 256;
                int row = G >> 4, gc = G & 15;
                cp16(vtB[buf ^ 1] + (row * VSR) * 4 + gc * 16,
                     Vtg + vbase + (size_t)row * S_ + kn + gc * 4);
            }
            cp_commit();
        }

        if (k0 <= qw + 15) {   // warp has at least one unmasked row
            const uint32_t kb = ksB[buf] + (b_row * KSR + b_col) * 4;
            const uint32_t vb = vtB[buf] + (b_row * VSR + b_col) * 4;

            // ---- S = Q K^T ----
            float s[8][4];
#pragma unroll
            for (int nt = 0; nt < 8; nt++)
#pragma unroll
                for (int t = 0; t < 4; t++) s[nt][t] = 0.f;

#pragma unroll
            for (int ks = 0; ks < 16; ks++) {
                uint32_t bb[8][2];
#pragma unroll
                for (int p = 0; p < 4; p++)
                    LDSM_X4(bb[2 * p][0], bb[2 * p][1], bb[2 * p + 1][0], bb[2 * p + 1][1],
                            kb + p * (16 * KSR * 4) + ks * 32);
#pragma unroll
                for (int nt = 0; nt < 8; nt++)
                    MMA_TF32(s[nt], qf[ks], bb[nt][0], bb[nt][1]);
            }

            // causal mask (diagonal tiles only)
            if (k0 + 63 > qw) {
                const int r0g = qw + (lane >> 2);
                const int c0g = k0 + (lane & 3) * 2;
#pragma unroll
                for (int nt = 0; nt < 8; nt++) {
                    const int c = c0g + nt * 8;
                    if (c     > r0g)     s[nt][0] = -3.0e38f;
                    if (c + 1 > r0g)     s[nt][1] = -3.0e38f;
                    if (c     > r0g + 8) s[nt][2] = -3.0e38f;
                    if (c + 1 > r0g + 8) s[nt][3] = -3.0e38f;
                }
            }

            // ---- online softmax ----
            float mx0 = -3.0e38f, mx1 = -3.0e38f;
#pragma unroll
            for (int nt = 0; nt < 8; nt++) {
                mx0 = fmaxf(mx0, fmaxf(s[nt][0], s[nt][1]));
                mx1 = fmaxf(mx1, fmaxf(s[nt][2], s[nt][3]));
            }
            mx0 = fmaxf(mx0, __shfl_xor_sync(0xffffffffu, mx0, 1));
            mx0 = fmaxf(mx0, __shfl_xor_sync(0xffffffffu, mx0, 2));
            mx1 = fmaxf(mx1, __shfl_xor_sync(0xffffffffu, mx1, 1));
            mx1 = fmaxf(mx1, __shfl_xor_sync(0xffffffffu, mx1, 2));

            const float mn0 = fmaxf(m0, mx0);
            const float mn1 = fmaxf(m1, mx1);
            const float cf0 = __expf(m0 - mn0);
            const float cf1 = __expf(m1 - mn1);

            float sum0 = 0.f, sum1 = 0.f;
            const int prow = warp * 16 + (lane >> 2);
            const int pcol = (lane & 3) * 2;
#pragma unroll
            for (int nt = 0; nt < 8; nt++) {
                float p0 = __expf(s[nt][0] - mn0);
                float p1 = __expf(s[nt][1] - mn0);
                float p2 = __expf(s[nt][2] - mn1);
                float p3 = __expf(s[nt][3] - mn1);
                sum0 += p0 + p1;
                sum1 += p2 + p3;
                uint32_t* d0 = &Ps[prow * VSR + pcol + nt * 8];
                d0[0] = f2tf(p0); d0[1] = f2tf(p1);
                uint32_t* d1 = &Ps[(prow + 8) * VSR + pcol + nt * 8];
                d1[0] = f2tf(p2); d1[1] = f2tf(p3);
            }
            sum0 += __shfl_xor_sync(0xffffffffu, sum0, 1);
            sum0 += __shfl_xor_sync(0xffffffffu, sum0, 2);
            sum1 += __shfl_xor_sync(0xffffffffu, sum1, 1);
            sum1 += __shfl_xor_sync(0xffffffffu, sum1, 2);

            m0 = mn0; m1 = mn1;
            l0 = l0 * cf0 + sum0;
            l1 = l1 * cf1 + sum1;

#pragma unroll
            for (int nt = 0; nt < 16; nt++) {
                of[nt][0] *= cf0; of[nt][1] *= cf0;
                of[nt][2] *= cf1; of[nt][3] *= cf1;
            }

            __syncwarp();   // Ps writes visible to ldmatrix across lanes

            // ---- O += P V ----
#pragma unroll
            for (int ks = 0; ks < 8; ks++) {
                uint32_t pa[4];
                LDSM_X4(pa[0], pa[1], pa[2], pa[3], pb + ks * 32);
#pragma unroll
                for (int np = 0; np < 8; np++) {
                    uint32_t v0, v1, v2, v3;
                    LDSM_X4(v0, v1, v2, v3, vb + np * (16 * VSR * 4) + ks * 32);
                    MMA_TF32(of[2 * np],     pa, v0, v1);
                    MMA_TF32(of[2 * np + 1], pa, v2, v3);
                }
            }
        }

        if (more) asm volatile("cp.async.wait_group 0;" ::: "memory");
        __syncthreads();
        buf ^= 1;
    }

    // ---- epilogue: write Y tf32-rounded (feeds O-projection mma) ----
    const float li0 = 1.0f / l0;
    const float li1 = 1.0f / l1;
    const int r0 = q0 + warp * 16 + (lane >> 2);
#pragma unroll
    for (int nt = 0; nt < 16; nt++) {
        const int c = nt * 8 + (lane & 3) * 2;
        float* p = Yg + base + (size_t)r0 * D_ + c;
        *(float2*)p = make_float2(__uint_as_float(f2tf(of[nt][0] * li0)),
                                  __uint_as_float(f2tf(of[nt][1] * li0)));
        *(float2*)(p + (size_t)8 * D_) =
            make_float2(__uint_as_float(f2tf(of[nt][2] * li1)),
                        __uint_as_float(f2tf(of[nt][3] * li1)));
    }
}

// ----------------------------------------------------------------------------
// kernel_launch
// ----------------------------------------------------------------------------
extern "C" void kernel_launch(void* const* d_in, const int* in_sizes, int n_in,
                              void* d_out, int out_size)
{
    const float* x  = (const float*)d_in[0];
    const float* Wq = (const float*)d_in[2];
    const float* Wk = (const float*)d_in[3];
    const float* Wv = (const float*)d_in[4];
    const float* Wo = (const float*)d_in[5];
    float* out = (float*)d_out;

    float *Q, *K, *V, *Vt, *Y, *Xt, *Wt;
    cudaGetSymbolAddress((void**)&Q,  g_Q);
    cudaGetSymbolAddress((void**)&K,  g_K);
    cudaGetSymbolAddress((void**)&V,  g_V);
    cudaGetSymbolAddress((void**)&Vt, g_Vt);
    cudaGetSymbolAddress((void**)&Y,  g_Y);
    cudaGetSymbolAddress((void**)&Xt, g_Xt);
    cudaGetSymbolAddress((void**)&Wt, g_Wt);
    float* Wqt = Wt;
    float* Wkt = Wt + (size_t)D_ * D_;
    float* Wvt = Wt + 2 * (size_t)D_ * D_;
    float* Wot = Wt + 3 * (size_t)D_ * D_;

    static int configured = 0;
    if (!configured) {
        cudaFuncSetAttribute(gemm_tf32,
                             cudaFuncAttributeMaxDynamicSharedMemorySize,
                             GEMM_SMEM_BYTES);
        cudaFuncSetAttribute(attn_tc,
                             cudaFuncAttributeMaxDynamicSharedMemorySize,
                             ATTN_SMEM_BYTES);
        configured = 1;
    }

    // pre-round operands to tf32 (rna) so in-HW truncation is exact
    const int nx4 = (ROWS * D_) / 4;
    const int nw4 = (D_ * D_) / 4;
    cvt_rna_k<<<(nx4 + 255) / 256, 256>>>((const float4*)x,  (float4*)Xt,  nx4);
    cvt_rna_k<<<(nw4 + 255) / 256, 256>>>((const float4*)Wq, (float4*)Wqt, nw4);
    cvt_rna_k<<<(nw4 + 255) / 256, 256>>>((const float4*)Wk, (float4*)Wkt, nw4);
    cvt_rna_k<<<(nw4 + 255) / 256, 256>>>((const float4*)Wv, (float4*)Wvt, nw4);
    cvt_rna_k<<<(nw4 + 255) / 256, 256>>>((const float4*)Wo, (float4*)Wot, nw4);

    dim3 gg(D_ / GBN, ROWS / GBM);   // (16, 32)
    dim3 tb(256);

    gemm_tf32<<<gg, tb, GEMM_SMEM_BYTES>>>(Xt, Wqt, Q, 1);
    gemm_tf32<<<gg, tb, GEMM_SMEM_BYTES>>>(Xt, Wkt, K, 1);
    gemm_tf32<<<gg, tb, GEMM_SMEM_BYTES>>>(Xt, Wvt, V, 1);

    transpose_k<<<dim3(S_ / 32, D_ / 32, B_), 256>>>(V, Vt);

    attn_tc<<<dim3(S_ / AQ, B_ * H_), tb, ATTN_SMEM_BYTES>>>(Q, K, Vt, Y);

    gemm_tf32<<<gg, tb, GEMM_SMEM_BYTES>>>(Y, Wot, out, 0);
}